// round 1
// baseline (speedup 1.0000x reference)
#include <cuda_runtime.h>
#include <cuda_fp16.h>
#include <mma.h>

using namespace nvcuda;

#define S_LEN  2048
#define BATCH  2
#define DMODEL 1024
#define NHEAD  16
#define DKH    64
#define MROWS  (S_LEN * BATCH)   // 4096

static constexpr float SCALE = 0.125f;  // 1/sqrt(64)

// ---------------- scratch (no allocations allowed) ----------------
__device__ __half g_Q[BATCH * NHEAD * S_LEN * DKH];   // [b][h][s][dk]
__device__ __half g_K[BATCH * NHEAD * S_LEN * DKH];
__device__ __half g_V[BATCH * NHEAD * S_LEN * DKH];
__device__ __half g_ctx[MROWS * DMODEL];              // [(s*B+b)][h*64+dk]

// =============================================================
// Projection GEMM: Y = X @ W^T + bias, fp32 in, fp16 out (permuted per-head)
// X: (4096, 1024) fp32 row-major. W: (1024, 1024) fp32 row-major (row = out feature).
// Out: g_{Q,K,V} layout [b][h][s][dk].
// Block: 128 threads (4 warps), tile 64x64, K-chunk 64.
// =============================================================
__global__ void __launch_bounds__(128) proj_qkv_kernel(
    const float* __restrict__ X, const float* __restrict__ W,
    const float* __restrict__ bias, __half* __restrict__ out)
{
    __shared__ __half As[64][72];
    __shared__ __half Bs[64][72];
    __shared__ float  Cs[64][68];

    const int m0 = blockIdx.y * 64;
    const int n0 = blockIdx.x * 64;
    const int tid  = threadIdx.x;
    const int warp = tid >> 5;
    const int wr = warp >> 1, wc = warp & 1;

    wmma::fragment<wmma::accumulator, 16, 16, 16, float> acc[2][2];
    #pragma unroll
    for (int i = 0; i < 2; i++)
        #pragma unroll
        for (int j = 0; j < 2; j++)
            wmma::fill_fragment(acc[i][j], 0.0f);

    for (int k0 = 0; k0 < DMODEL; k0 += 64) {
        // stage A tile (64x64 fp32 -> half): 1024 float4, 8 per thread
        #pragma unroll
        for (int i = 0; i < 8; i++) {
            int idx = i * 128 + tid;
            int r = idx >> 4, c4 = (idx & 15) << 2;
            float4 v = *(const float4*)(X + (size_t)(m0 + r) * DMODEL + k0 + c4);
            *(half2*)&As[r][c4]     = __floats2half2_rn(v.x, v.y);
            *(half2*)&As[r][c4 + 2] = __floats2half2_rn(v.z, v.w);
        }
        // stage B tile from W (rows = output features)
        #pragma unroll
        for (int i = 0; i < 8; i++) {
            int idx = i * 128 + tid;
            int r = idx >> 4, c4 = (idx & 15) << 2;
            float4 v = *(const float4*)(W + (size_t)(n0 + r) * DMODEL + k0 + c4);
            *(half2*)&Bs[r][c4]     = __floats2half2_rn(v.x, v.y);
            *(half2*)&Bs[r][c4 + 2] = __floats2half2_rn(v.z, v.w);
        }
        __syncthreads();

        #pragma unroll
        for (int kk = 0; kk < 64; kk += 16) {
            wmma::fragment<wmma::matrix_a, 16, 16, 16, __half, wmma::row_major> a[2];
            wmma::load_matrix_sync(a[0], &As[wr * 32][kk], 72);
            wmma::load_matrix_sync(a[1], &As[wr * 32 + 16][kk], 72);
            wmma::fragment<wmma::matrix_b, 16, 16, 16, __half, wmma::col_major> b[2];
            wmma::load_matrix_sync(b[0], &Bs[wc * 32][kk], 72);
            wmma::load_matrix_sync(b[1], &Bs[wc * 32 + 16][kk], 72);
            #pragma unroll
            for (int i = 0; i < 2; i++)
                #pragma unroll
                for (int j = 0; j < 2; j++)
                    wmma::mma_sync(acc[i][j], a[i], b[j], acc[i][j]);
        }
        __syncthreads();
    }

    #pragma unroll
    for (int i = 0; i < 2; i++)
        #pragma unroll
        for (int j = 0; j < 2; j++)
            wmma::store_matrix_sync(&Cs[wr * 32 + i * 16][wc * 32 + j * 16],
                                    acc[i][j], 68, wmma::mem_row_major);
    __syncthreads();

    #pragma unroll
    for (int i = 0; i < 32; i++) {
        int idx = i * 128 + tid;
        int r = idx >> 6, c = idx & 63;
        float val = Cs[r][c] + bias[n0 + c];
        int m = m0 + r;
        int s = m >> 1, b = m & 1;           // m = s*B + b, B=2
        int n = n0 + c;
        int h = n >> 6, dk = n & 63;
        out[((((size_t)b * NHEAD + h) * S_LEN + s) << 6) + dk] = __float2half(val);
    }
}

// =============================================================
// Output projection: d_out = ctx(fp16) @ Wo^T + bo, fp32 out row-major
// =============================================================
__global__ void __launch_bounds__(128) outproj_kernel(
    const __half* __restrict__ Xh, const float* __restrict__ W,
    const float* __restrict__ bias, float* __restrict__ out)
{
    __shared__ __half As[64][72];
    __shared__ __half Bs[64][72];
    __shared__ float  Cs[64][68];

    const int m0 = blockIdx.y * 64;
    const int n0 = blockIdx.x * 64;
    const int tid  = threadIdx.x;
    const int warp = tid >> 5;
    const int wr = warp >> 1, wc = warp & 1;

    wmma::fragment<wmma::accumulator, 16, 16, 16, float> acc[2][2];
    #pragma unroll
    for (int i = 0; i < 2; i++)
        #pragma unroll
        for (int j = 0; j < 2; j++)
            wmma::fill_fragment(acc[i][j], 0.0f);

    for (int k0 = 0; k0 < DMODEL; k0 += 64) {
        // A tile from half source: 2048 half2, 16 per thread
        #pragma unroll
        for (int i = 0; i < 16; i++) {
            int idx = i * 128 + tid;
            int r = idx >> 5, c2 = (idx & 31) << 1;
            *(half2*)&As[r][c2] = *(const half2*)(Xh + (size_t)(m0 + r) * DMODEL + k0 + c2);
        }
        #pragma unroll
        for (int i = 0; i < 8; i++) {
            int idx = i * 128 + tid;
            int r = idx >> 4, c4 = (idx & 15) << 2;
            float4 v = *(const float4*)(W + (size_t)(n0 + r) * DMODEL + k0 + c4);
            *(half2*)&Bs[r][c4]     = __floats2half2_rn(v.x, v.y);
            *(half2*)&Bs[r][c4 + 2] = __floats2half2_rn(v.z, v.w);
        }
        __syncthreads();

        #pragma unroll
        for (int kk = 0; kk < 64; kk += 16) {
            wmma::fragment<wmma::matrix_a, 16, 16, 16, __half, wmma::row_major> a[2];
            wmma::load_matrix_sync(a[0], &As[wr * 32][kk], 72);
            wmma::load_matrix_sync(a[1], &As[wr * 32 + 16][kk], 72);
            wmma::fragment<wmma::matrix_b, 16, 16, 16, __half, wmma::col_major> b[2];
            wmma::load_matrix_sync(b[0], &Bs[wc * 32][kk], 72);
            wmma::load_matrix_sync(b[1], &Bs[wc * 32 + 16][kk], 72);
            #pragma unroll
            for (int i = 0; i < 2; i++)
                #pragma unroll
                for (int j = 0; j < 2; j++)
                    wmma::mma_sync(acc[i][j], a[i], b[j], acc[i][j]);
        }
        __syncthreads();
    }

    #pragma unroll
    for (int i = 0; i < 2; i++)
        #pragma unroll
        for (int j = 0; j < 2; j++)
            wmma::store_matrix_sync(&Cs[wr * 32 + i * 16][wc * 32 + j * 16],
                                    acc[i][j], 68, wmma::mem_row_major);
    __syncthreads();

    #pragma unroll
    for (int i = 0; i < 32; i++) {
        int idx = i * 128 + tid;
        int r = idx >> 6, c = idx & 63;
        out[(size_t)(m0 + r) * DMODEL + n0 + c] = Cs[r][c] + bias[n0 + c];
    }
}

// =============================================================
// Flash attention per (b,h): Q tile 64 rows, KV tiles of 64, online softmax.
// Block: 128 threads (4 warps). Dynamic smem ~61KB.
// =============================================================
#define SM_QS 0
#define SM_KS 9216
#define SM_VS 18432
#define SM_SS 27648
#define SM_OS 45056
#define SM_TOTAL 62464

__global__ void __launch_bounds__(128) attn_kernel(
    const __half* __restrict__ Qg_, const __half* __restrict__ Kg_,
    const __half* __restrict__ Vg_, __half* __restrict__ ctx)
{
    extern __shared__ char smbuf[];
    __half (*Qs)[72] = (__half(*)[72])(smbuf + SM_QS);
    __half (*Ks)[72] = (__half(*)[72])(smbuf + SM_KS);  // reused for P tile
    __half (*Vs)[72] = (__half(*)[72])(smbuf + SM_VS);
    float  (*Ss)[68] = (float (*)[68])(smbuf + SM_SS);
    float  (*Os)[68] = (float (*)[68])(smbuf + SM_OS);

    const int q0 = blockIdx.x * 64;
    const int h  = blockIdx.y;
    const int b  = blockIdx.z;
    const size_t head_off = ((size_t)b * NHEAD + h) * S_LEN * DKH;
    const __half* Qg = Qg_ + head_off;
    const __half* Kg = Kg_ + head_off;
    const __half* Vg = Vg_ + head_off;

    const int tid = threadIdx.x;
    const int warp = tid >> 5;

    // load Q tile: 2048 half2, 16 per thread
    #pragma unroll
    for (int i = 0; i < 16; i++) {
        int idx = i * 128 + tid;
        int r = idx >> 5, c2 = (idx & 31) << 1;
        *(half2*)&Qs[r][c2] = *(const half2*)(Qg + (q0 + r) * DKH + c2);
    }
    // zero O accumulator
    #pragma unroll
    for (int i = 0; i < 32; i++) {
        int idx = i * 128 + tid;
        Os[idx >> 6][idx & 63] = 0.0f;
    }

    float m_i = -1e30f, l_i = 0.0f;
    const int row = tid;  // valid for tid < 64 (row owner)

    for (int j0 = 0; j0 < S_LEN; j0 += 64) {
        __syncthreads();  // protect Ks/Vs/Qs from previous phase before overwrite
        // load K, V tiles
        #pragma unroll
        for (int i = 0; i < 16; i++) {
            int idx = i * 128 + tid;
            int r = idx >> 5, c2 = (idx & 31) << 1;
            *(half2*)&Ks[r][c2] = *(const half2*)(Kg + (j0 + r) * DKH + c2);
            *(half2*)&Vs[r][c2] = *(const half2*)(Vg + (j0 + r) * DKH + c2);
        }
        __syncthreads();

        // S = scale * Q @ K^T  (each warp: 16 rows x 64 cols)
        {
            wmma::fragment<wmma::accumulator, 16, 16, 16, float> c[4];
            #pragma unroll
            for (int nt = 0; nt < 4; nt++) wmma::fill_fragment(c[nt], 0.0f);
            #pragma unroll
            for (int kk = 0; kk < 64; kk += 16) {
                wmma::fragment<wmma::matrix_a, 16, 16, 16, __half, wmma::row_major> a;
                wmma::load_matrix_sync(a, &Qs[warp * 16][kk], 72);
                #pragma unroll
                for (int nt = 0; nt < 4; nt++) {
                    wmma::fragment<wmma::matrix_b, 16, 16, 16, __half, wmma::col_major> bf;
                    wmma::load_matrix_sync(bf, &Ks[nt * 16][kk], 72);
                    wmma::mma_sync(c[nt], a, bf, c[nt]);
                }
            }
            #pragma unroll
            for (int nt = 0; nt < 4; nt++) {
                #pragma unroll
                for (int e = 0; e < c[nt].num_elements; e++) c[nt].x[e] *= SCALE;
                wmma::store_matrix_sync(&Ss[warp * 16][nt * 16], c[nt], 68, wmma::mem_row_major);
            }
        }
        __syncthreads();

        // online softmax: threads 0..63 each own one row; write P (half) into Ks
        if (tid < 64) {
            float mt = -1e30f;
            #pragma unroll 8
            for (int c = 0; c < 64; c++) mt = fmaxf(mt, Ss[row][c]);
            float m_new = fmaxf(m_i, mt);
            float alpha = __expf(m_i - m_new);
            float lsum = 0.0f;
            #pragma unroll 8
            for (int c = 0; c < 64; c++) {
                float p = __expf(Ss[row][c] - m_new);
                lsum += p;
                Ks[row][c] = __float2half(p);
            }
            l_i = l_i * alpha + lsum;
            m_i = m_new;
            #pragma unroll 8
            for (int c = 0; c < 64; c++) Os[row][c] *= alpha;
        }
        __syncthreads();

        // O += P @ V
        {
            wmma::fragment<wmma::matrix_a, 16, 16, 16, __half, wmma::row_major> a[4];
            #pragma unroll
            for (int kk = 0; kk < 4; kk++)
                wmma::load_matrix_sync(a[kk], &Ks[warp * 16][kk * 16], 72);
            #pragma unroll
            for (int nt = 0; nt < 4; nt++) {
                wmma::fragment<wmma::accumulator, 16, 16, 16, float> accf;
                wmma::load_matrix_sync(accf, &Os[warp * 16][nt * 16], 68, wmma::mem_row_major);
                #pragma unroll
                for (int kk = 0; kk < 4; kk++) {
                    wmma::fragment<wmma::matrix_b, 16, 16, 16, __half, wmma::row_major> bf;
                    wmma::load_matrix_sync(bf, &Vs[kk * 16][nt * 16], 72);
                    wmma::mma_sync(accf, a[kk], bf, accf);
                }
                wmma::store_matrix_sync(&Os[warp * 16][nt * 16], accf, 68, wmma::mem_row_major);
            }
        }
    }
    __syncthreads();

    // epilogue: normalize and write context (fp16) in (s*B+b, h*64+dk) layout
    if (tid < 64) {
        float inv = 1.0f / l_i;
        int s = q0 + row;
        __half* dst = ctx + ((size_t)s * BATCH + b) * DMODEL + h * DKH;
        #pragma unroll 8
        for (int c = 0; c < 64; c++) dst[c] = __float2half(Os[row][c] * inv);
    }
}

// =============================================================
extern "C" void kernel_launch(void* const* d_in, const int* in_sizes, int n_in,
                              void* d_out, int out_size)
{
    const float* q  = (const float*)d_in[0];
    const float* k  = (const float*)d_in[1];
    const float* v  = (const float*)d_in[2];
    const float* wq = (const float*)d_in[3];
    const float* bq = (const float*)d_in[4];
    const float* wk = (const float*)d_in[5];
    const float* bk = (const float*)d_in[6];
    const float* wv = (const float*)d_in[7];
    const float* bv = (const float*)d_in[8];
    const float* wo = (const float*)d_in[9];
    const float* bo = (const float*)d_in[10];
    float* out = (float*)d_out;

    void *pQ, *pK, *pV, *pC;
    cudaGetSymbolAddress(&pQ, g_Q);
    cudaGetSymbolAddress(&pK, g_K);
    cudaGetSymbolAddress(&pV, g_V);
    cudaGetSymbolAddress(&pC, g_ctx);

    cudaFuncSetAttribute(attn_kernel, cudaFuncAttributeMaxDynamicSharedMemorySize, SM_TOTAL);

    dim3 gp(DMODEL / 64, MROWS / 64);  // (16, 64)
    proj_qkv_kernel<<<gp, 128>>>(q, wq, bq, (__half*)pQ);
    proj_qkv_kernel<<<gp, 128>>>(k, wk, bk, (__half*)pK);
    proj_qkv_kernel<<<gp, 128>>>(v, wv, bv, (__half*)pV);

    dim3 ga(S_LEN / 64, NHEAD, BATCH);  // (32, 16, 2)
    attn_kernel<<<ga, 128, SM_TOTAL>>>((const __half*)pQ, (const __half*)pK,
                                       (const __half*)pV, (__half*)pC);

    outproj_kernel<<<gp, 128>>>((const __half*)pC, wo, bo, out);
}

// round 2
// speedup vs baseline: 1.6423x; 1.6423x over previous
#include <cuda_runtime.h>
#include <cuda_fp16.h>
#include <mma.h>
#include <cstdint>

using namespace nvcuda;

#define S_LEN  2048
#define BATCH  2
#define DMODEL 1024
#define NHEAD  16
#define DKH    64
#define MROWS  (S_LEN * BATCH)   // 4096

static constexpr float SCALE = 0.125f;  // 1/sqrt(64)

// ---------------- scratch (no allocations allowed) ----------------
__device__ __half g_Q[BATCH * NHEAD * S_LEN * DKH];   // [b][h][s][dk]
__device__ __half g_K[BATCH * NHEAD * S_LEN * DKH];
__device__ __half g_V[BATCH * NHEAD * S_LEN * DKH];
__device__ __half g_ctx[MROWS * DMODEL];              // [(s*B+b)][h*64+dk]

// ---------------- PTX helpers ----------------
__device__ __forceinline__ uint32_t smem_u32(const void* p) {
    return (uint32_t)__cvta_generic_to_shared(p);
}

#define LDMX4(r0, r1, r2, r3, addr) \
    asm volatile("ldmatrix.sync.aligned.m8n8.x4.shared.b16 {%0,%1,%2,%3}, [%4];" \
                 : "=r"(r0), "=r"(r1), "=r"(r2), "=r"(r3) : "r"(addr))

#define LDMX4T(r0, r1, r2, r3, addr) \
    asm volatile("ldmatrix.sync.aligned.m8n8.x4.trans.shared.b16 {%0,%1,%2,%3}, [%4];" \
                 : "=r"(r0), "=r"(r1), "=r"(r2), "=r"(r3) : "r"(addr))

#define MMA16816(C, A, b0, b1) \
    asm volatile("mma.sync.aligned.m16n8k16.row.col.f32.f16.f16.f32 " \
                 "{%0,%1,%2,%3}, {%4,%5,%6,%7}, {%8,%9}, {%0,%1,%2,%3};" \
                 : "+f"((C)[0]), "+f"((C)[1]), "+f"((C)[2]), "+f"((C)[3]) \
                 : "r"((A)[0]), "r"((A)[1]), "r"((A)[2]), "r"((A)[3]), \
                   "r"(b0), "r"(b1))

#define CP_ASYNC16(dst, src) \
    asm volatile("cp.async.cg.shared.global [%0], [%1], 16;" :: "r"(dst), "l"(src))
#define CP_COMMIT() asm volatile("cp.async.commit_group;")
#define CP_WAIT_ALL() asm volatile("cp.async.wait_group 0;")

__device__ __forceinline__ uint32_t pack_h2(float x, float y) {
    __half2 h = __floats2half2_rn(x, y);
    return *reinterpret_cast<uint32_t*>(&h);
}

// =============================================================
// Projection GEMM: Y = X @ W^T + bias, fp32 in, fp16 out (permuted per-head)
// =============================================================
__global__ void __launch_bounds__(128) proj_qkv_kernel(
    const float* __restrict__ X, const float* __restrict__ W,
    const float* __restrict__ bias, __half* __restrict__ out)
{
    __shared__ __half As[64][72];
    __shared__ __half Bs[64][72];
    __shared__ float  Cs[64][68];

    const int m0 = blockIdx.y * 64;
    const int n0 = blockIdx.x * 64;
    const int tid  = threadIdx.x;
    const int warp = tid >> 5;
    const int wr = warp >> 1, wc = warp & 1;

    wmma::fragment<wmma::accumulator, 16, 16, 16, float> acc[2][2];
    #pragma unroll
    for (int i = 0; i < 2; i++)
        #pragma unroll
        for (int j = 0; j < 2; j++)
            wmma::fill_fragment(acc[i][j], 0.0f);

    for (int k0 = 0; k0 < DMODEL; k0 += 64) {
        #pragma unroll
        for (int i = 0; i < 8; i++) {
            int idx = i * 128 + tid;
            int r = idx >> 4, c4 = (idx & 15) << 2;
            float4 v = *(const float4*)(X + (size_t)(m0 + r) * DMODEL + k0 + c4);
            *(half2*)&As[r][c4]     = __floats2half2_rn(v.x, v.y);
            *(half2*)&As[r][c4 + 2] = __floats2half2_rn(v.z, v.w);
        }
        #pragma unroll
        for (int i = 0; i < 8; i++) {
            int idx = i * 128 + tid;
            int r = idx >> 4, c4 = (idx & 15) << 2;
            float4 v = *(const float4*)(W + (size_t)(n0 + r) * DMODEL + k0 + c4);
            *(half2*)&Bs[r][c4]     = __floats2half2_rn(v.x, v.y);
            *(half2*)&Bs[r][c4 + 2] = __floats2half2_rn(v.z, v.w);
        }
        __syncthreads();

        #pragma unroll
        for (int kk = 0; kk < 64; kk += 16) {
            wmma::fragment<wmma::matrix_a, 16, 16, 16, __half, wmma::row_major> a[2];
            wmma::load_matrix_sync(a[0], &As[wr * 32][kk], 72);
            wmma::load_matrix_sync(a[1], &As[wr * 32 + 16][kk], 72);
            wmma::fragment<wmma::matrix_b, 16, 16, 16, __half, wmma::col_major> b[2];
            wmma::load_matrix_sync(b[0], &Bs[wc * 32][kk], 72);
            wmma::load_matrix_sync(b[1], &Bs[wc * 32 + 16][kk], 72);
            #pragma unroll
            for (int i = 0; i < 2; i++)
                #pragma unroll
                for (int j = 0; j < 2; j++)
                    wmma::mma_sync(acc[i][j], a[i], b[j], acc[i][j]);
        }
        __syncthreads();
    }

    #pragma unroll
    for (int i = 0; i < 2; i++)
        #pragma unroll
        for (int j = 0; j < 2; j++)
            wmma::store_matrix_sync(&Cs[wr * 32 + i * 16][wc * 32 + j * 16],
                                    acc[i][j], 68, wmma::mem_row_major);
    __syncthreads();

    #pragma unroll
    for (int i = 0; i < 32; i++) {
        int idx = i * 128 + tid;
        int r = idx >> 6, c = idx & 63;
        float val = Cs[r][c] + bias[n0 + c];
        int m = m0 + r;
        int s = m >> 1, b = m & 1;           // m = s*B + b, B=2
        int n = n0 + c;
        int h = n >> 6, dk = n & 63;
        out[((((size_t)b * NHEAD + h) * S_LEN + s) << 6) + dk] = __float2half(val);
    }
}

// =============================================================
// Output projection: d_out = ctx(fp16) @ Wo^T + bo, fp32 out
// =============================================================
__global__ void __launch_bounds__(128) outproj_kernel(
    const __half* __restrict__ Xh, const float* __restrict__ W,
    const float* __restrict__ bias, float* __restrict__ out)
{
    __shared__ __half As[64][72];
    __shared__ __half Bs[64][72];
    __shared__ float  Cs[64][68];

    const int m0 = blockIdx.y * 64;
    const int n0 = blockIdx.x * 64;
    const int tid  = threadIdx.x;
    const int warp = tid >> 5;
    const int wr = warp >> 1, wc = warp & 1;

    wmma::fragment<wmma::accumulator, 16, 16, 16, float> acc[2][2];
    #pragma unroll
    for (int i = 0; i < 2; i++)
        #pragma unroll
        for (int j = 0; j < 2; j++)
            wmma::fill_fragment(acc[i][j], 0.0f);

    for (int k0 = 0; k0 < DMODEL; k0 += 64) {
        #pragma unroll
        for (int i = 0; i < 16; i++) {
            int idx = i * 128 + tid;
            int r = idx >> 5, c2 = (idx & 31) << 1;
            *(half2*)&As[r][c2] = *(const half2*)(Xh + (size_t)(m0 + r) * DMODEL + k0 + c2);
        }
        #pragma unroll
        for (int i = 0; i < 8; i++) {
            int idx = i * 128 + tid;
            int r = idx >> 4, c4 = (idx & 15) << 2;
            float4 v = *(const float4*)(W + (size_t)(n0 + r) * DMODEL + k0 + c4);
            *(half2*)&Bs[r][c4]     = __floats2half2_rn(v.x, v.y);
            *(half2*)&Bs[r][c4 + 2] = __floats2half2_rn(v.z, v.w);
        }
        __syncthreads();

        #pragma unroll
        for (int kk = 0; kk < 64; kk += 16) {
            wmma::fragment<wmma::matrix_a, 16, 16, 16, __half, wmma::row_major> a[2];
            wmma::load_matrix_sync(a[0], &As[wr * 32][kk], 72);
            wmma::load_matrix_sync(a[1], &As[wr * 32 + 16][kk], 72);
            wmma::fragment<wmma::matrix_b, 16, 16, 16, __half, wmma::col_major> b[2];
            wmma::load_matrix_sync(b[0], &Bs[wc * 32][kk], 72);
            wmma::load_matrix_sync(b[1], &Bs[wc * 32 + 16][kk], 72);
            #pragma unroll
            for (int i = 0; i < 2; i++)
                #pragma unroll
                for (int j = 0; j < 2; j++)
                    wmma::mma_sync(acc[i][j], a[i], b[j], acc[i][j]);
        }
        __syncthreads();
    }

    #pragma unroll
    for (int i = 0; i < 2; i++)
        #pragma unroll
        for (int j = 0; j < 2; j++)
            wmma::store_matrix_sync(&Cs[wr * 32 + i * 16][wc * 32 + j * 16],
                                    acc[i][j], 68, wmma::mem_row_major);
    __syncthreads();

    #pragma unroll
    for (int i = 0; i < 32; i++) {
        int idx = i * 128 + tid;
        int r = idx >> 6, c = idx & 63;
        out[(size_t)(m0 + r) * DMODEL + n0 + c] = Cs[r][c] + bias[n0 + c];
    }
}

// =============================================================
// Register-resident flash attention.
// Block: 256 threads (8 warps), Q tile 128 rows (16/warp), KV tile 64.
// mma.sync.m16n8k16 + ldmatrix; online softmax fully in registers.
// Smem: Q staging + double-buffered K/V via cp.async.
// =============================================================
#define BQ 128
#define BK 64
#define APITCH 72   // halves per smem row (144B, 16B-aligned, conflict-free ldmatrix)

#define SM_Q  0
#define SM_K  (BQ * APITCH * 2)                    // 18432
#define SM_V  (SM_K + 2 * BK * APITCH * 2)         // 18432 + 18432
#define SM_ATTN_TOTAL (SM_V + 2 * BK * APITCH * 2) // 55296

__global__ void __launch_bounds__(256) attn_kernel(
    const __half* __restrict__ Qg_, const __half* __restrict__ Kg_,
    const __half* __restrict__ Vg_, __half* __restrict__ ctx)
{
    extern __shared__ char smb[];
    __half (*Qs)[APITCH] = (__half(*)[APITCH])(smb + SM_Q);
    __half (*Ks)[BK][APITCH] = (__half(*)[BK][APITCH])(smb + SM_K);
    __half (*Vs)[BK][APITCH] = (__half(*)[BK][APITCH])(smb + SM_V);

    const int q0 = blockIdx.x * BQ;
    const int h  = blockIdx.y;
    const int b  = blockIdx.z;
    const size_t head_off = ((size_t)b * NHEAD + h) * S_LEN * DKH;
    const __half* Qg = Qg_ + head_off;
    const __half* Kg = Kg_ + head_off;
    const __half* Vg = Vg_ + head_off;

    const int tid  = threadIdx.x;
    const int warp = tid >> 5;
    const int lane = tid & 31;
    const int g = lane >> 2;     // quad group: rows g, g+8 (warp-local)
    const int t = lane & 3;      // col pair 2t, 2t+1

    // ---- load Q tile to smem (128 rows x 64 halves), 16B chunks ----
    #pragma unroll
    for (int i = 0; i < 4; i++) {
        int idx = i * 256 + tid;           // 0..1023
        int r = idx >> 3, c8 = (idx & 7) * 8;
        *(uint4*)&Qs[r][c8] = *(const uint4*)(Qg + (size_t)(q0 + r) * DKH + c8);
    }

    // ---- prefetch KV tile 0 ----
    {
        #pragma unroll
        for (int i = 0; i < 2; i++) {
            int idx = i * 256 + tid;       // 0..511
            int r = idx >> 3, c = (idx & 7) * 8;
            CP_ASYNC16(smem_u32(&Ks[0][r][c]), Kg + (size_t)r * DKH + c);
            CP_ASYNC16(smem_u32(&Vs[0][r][c]), Vg + (size_t)r * DKH + c);
        }
        CP_COMMIT();
    }
    __syncthreads();

    // ---- ldmatrix Q into A-fragments: qf[ktile u][4 regs] ----
    uint32_t qf[4][4];
    {
        int lrow = warp * 16 + ((lane >> 3) & 1) * 8 + (lane & 7);
        int lcol = (lane >> 4) * 8;
        #pragma unroll
        for (int u = 0; u < 4; u++) {
            uint32_t addr = smem_u32(&Qs[lrow][16 * u + lcol]);
            LDMX4(qf[u][0], qf[u][1], qf[u][2], qf[u][3], addr);
        }
    }

    float m0 = -1e30f, m1 = -1e30f, l0 = 0.0f, l1 = 0.0f;
    float o[8][4];
    #pragma unroll
    for (int j = 0; j < 8; j++)
        #pragma unroll
        for (int e = 0; e < 4; e++) o[j][e] = 0.0f;

    const int lrow = ((lane >> 3) & 1) * 8 + (lane & 7);  // row within 16-row group
    const int lcol = (lane >> 4) * 8;                     // col offset within 16-col group

    const int NT = S_LEN / BK;  // 32
    for (int it = 0; it < NT; ++it) {
        const int st = it & 1;
        CP_WAIT_ALL();
        __syncthreads();

        // prefetch next tile into the other stage (safe: sync above)
        if (it + 1 < NT) {
            const int j1 = (it + 1) * BK;
            #pragma unroll
            for (int i = 0; i < 2; i++) {
                int idx = i * 256 + tid;
                int r = idx >> 3, c = (idx & 7) * 8;
                CP_ASYNC16(smem_u32(&Ks[st ^ 1][r][c]), Kg + (size_t)(j1 + r) * DKH + c);
                CP_ASYNC16(smem_u32(&Vs[st ^ 1][r][c]), Vg + (size_t)(j1 + r) * DKH + c);
            }
            CP_COMMIT();
        }

        // ---- S = Q @ K^T (register acc, 8 n-tiles of 8 keys each) ----
        float sc[8][4];
        #pragma unroll
        for (int j = 0; j < 8; j++)
            #pragma unroll
            for (int e = 0; e < 4; e++) sc[j][e] = 0.0f;

        #pragma unroll
        for (int kg = 0; kg < 4; kg++) {      // key groups of 16
            #pragma unroll
            for (int u = 0; u < 4; u++) {     // dk k-tiles of 16
                uint32_t r0, r1, r2, r3;
                uint32_t addr = smem_u32(&Ks[st][16 * kg + lrow][16 * u + lcol]);
                LDMX4(r0, r1, r2, r3, addr);
                MMA16816(sc[2 * kg],     qf[u], r0, r2);
                MMA16816(sc[2 * kg + 1], qf[u], r1, r3);
            }
        }

        // ---- online softmax (registers + quad shuffles) ----
        #pragma unroll
        for (int j = 0; j < 8; j++)
            #pragma unroll
            for (int e = 0; e < 4; e++) sc[j][e] *= SCALE;

        float mt0 = -1e30f, mt1 = -1e30f;
        #pragma unroll
        for (int j = 0; j < 8; j++) {
            mt0 = fmaxf(mt0, fmaxf(sc[j][0], sc[j][1]));
            mt1 = fmaxf(mt1, fmaxf(sc[j][2], sc[j][3]));
        }
        mt0 = fmaxf(mt0, __shfl_xor_sync(0xffffffffu, mt0, 1));
        mt0 = fmaxf(mt0, __shfl_xor_sync(0xffffffffu, mt0, 2));
        mt1 = fmaxf(mt1, __shfl_xor_sync(0xffffffffu, mt1, 1));
        mt1 = fmaxf(mt1, __shfl_xor_sync(0xffffffffu, mt1, 2));

        float mn0 = fmaxf(m0, mt0), mn1 = fmaxf(m1, mt1);
        float a0 = __expf(m0 - mn0), a1 = __expf(m1 - mn1);
        m0 = mn0; m1 = mn1;

        float s0 = 0.0f, s1 = 0.0f;
        uint32_t pf[4][4];   // P as A-fragments for PV
        #pragma unroll
        for (int j = 0; j < 8; j++) {
            float p0 = __expf(sc[j][0] - m0);
            float p1 = __expf(sc[j][1] - m0);
            float p2 = __expf(sc[j][2] - m1);
            float p3 = __expf(sc[j][3] - m1);
            s0 += p0 + p1;
            s1 += p2 + p3;
            int u = j >> 1, hi = j & 1;
            pf[u][2 * hi]     = pack_h2(p0, p1);   // a0 / a2
            pf[u][2 * hi + 1] = pack_h2(p2, p3);   // a1 / a3
        }
        s0 += __shfl_xor_sync(0xffffffffu, s0, 1);
        s0 += __shfl_xor_sync(0xffffffffu, s0, 2);
        s1 += __shfl_xor_sync(0xffffffffu, s1, 1);
        s1 += __shfl_xor_sync(0xffffffffu, s1, 2);
        l0 = l0 * a0 + s0;
        l1 = l1 * a1 + s1;

        #pragma unroll
        for (int j = 0; j < 8; j++) {
            o[j][0] *= a0; o[j][1] *= a0;
            o[j][2] *= a1; o[j][3] *= a1;
        }

        // ---- O += P @ V (V via ldmatrix.trans) ----
        #pragma unroll
        for (int u = 0; u < 4; u++) {          // key k-tiles of 16
            #pragma unroll
            for (int jp = 0; jp < 4; jp++) {   // dk pairs of 16
                uint32_t r0, r1, r2, r3;
                uint32_t addr = smem_u32(&Vs[st][16 * u + lrow][16 * jp + lcol]);
                LDMX4T(r0, r1, r2, r3, addr);
                MMA16816(o[2 * jp],     pf[u], r0, r1);
                MMA16816(o[2 * jp + 1], pf[u], r2, r3);
            }
        }
    }

    // ---- epilogue: normalize, write ctx half2 ----
    float inv0 = 1.0f / l0, inv1 = 1.0f / l1;
    int s_row0 = q0 + warp * 16 + g;
    int s_row1 = s_row0 + 8;
    __half* base0 = ctx + ((size_t)s_row0 * BATCH + b) * DMODEL + h * DKH;
    __half* base1 = ctx + ((size_t)s_row1 * BATCH + b) * DMODEL + h * DKH;
    #pragma unroll
    for (int j = 0; j < 8; j++) {
        int c = 8 * j + 2 * t;
        *(__half2*)(base0 + c) = __floats2half2_rn(o[j][0] * inv0, o[j][1] * inv0);
        *(__half2*)(base1 + c) = __floats2half2_rn(o[j][2] * inv1, o[j][3] * inv1);
    }
}

// =============================================================
extern "C" void kernel_launch(void* const* d_in, const int* in_sizes, int n_in,
                              void* d_out, int out_size)
{
    const float* q  = (const float*)d_in[0];
    const float* k  = (const float*)d_in[1];
    const float* v  = (const float*)d_in[2];
    const float* wq = (const float*)d_in[3];
    const float* bq = (const float*)d_in[4];
    const float* wk = (const float*)d_in[5];
    const float* bk = (const float*)d_in[6];
    const float* wv = (const float*)d_in[7];
    const float* bv = (const float*)d_in[8];
    const float* wo = (const float*)d_in[9];
    const float* bo = (const float*)d_in[10];
    float* out = (float*)d_out;

    void *pQ, *pK, *pV, *pC;
    cudaGetSymbolAddress(&pQ, g_Q);
    cudaGetSymbolAddress(&pK, g_K);
    cudaGetSymbolAddress(&pV, g_V);
    cudaGetSymbolAddress(&pC, g_ctx);

    cudaFuncSetAttribute(attn_kernel, cudaFuncAttributeMaxDynamicSharedMemorySize,
                         SM_ATTN_TOTAL);

    dim3 gp(DMODEL / 64, MROWS / 64);  // (16, 64)
    proj_qkv_kernel<<<gp, 128>>>(q, wq, bq, (__half*)pQ);
    proj_qkv_kernel<<<gp, 128>>>(k, wk, bk, (__half*)pK);
    proj_qkv_kernel<<<gp, 128>>>(v, wv, bv, (__half*)pV);

    dim3 ga(S_LEN / BQ, NHEAD, BATCH);  // (16, 16, 2)
    attn_kernel<<<ga, 256, SM_ATTN_TOTAL>>>((const __half*)pQ, (const __half*)pK,
                                            (const __half*)pV, (__half*)pC);

    outproj_kernel<<<gp, 128>>>((const __half*)pC, wo, bo, out);
}

// round 3
// speedup vs baseline: 1.9987x; 1.2170x over previous
#include <cuda_runtime.h>
#include <cuda_fp16.h>
#include <cstdint>

#define S_LEN  2048
#define BATCH  2
#define DMODEL 1024
#define NHEAD  16
#define DKH    64
#define MROWS  (S_LEN * BATCH)   // 4096

static constexpr float SCALE = 0.125f;  // 1/sqrt(64)

// ---------------- scratch (no allocations allowed) ----------------
__device__ __half g_Q[BATCH * NHEAD * S_LEN * DKH];   // [b][h][s][dk]
__device__ __half g_K[BATCH * NHEAD * S_LEN * DKH];
__device__ __half g_V[BATCH * NHEAD * S_LEN * DKH];
__device__ __half g_ctx[MROWS * DMODEL];              // [(s*B+b)][h*64+dk]
__device__ __half g_Xq[MROWS * DMODEL];               // fp16 activations
__device__ __half g_Xk[MROWS * DMODEL];
__device__ __half g_Xv[MROWS * DMODEL];
__device__ __half g_Wq[DMODEL * DMODEL];              // fp16 weights
__device__ __half g_Wk[DMODEL * DMODEL];
__device__ __half g_Wv[DMODEL * DMODEL];
__device__ __half g_Wo[DMODEL * DMODEL];

// ---------------- PTX helpers ----------------
__device__ __forceinline__ uint32_t smem_u32(const void* p) {
    return (uint32_t)__cvta_generic_to_shared(p);
}

#define LDMX4(r0, r1, r2, r3, addr) \
    asm volatile("ldmatrix.sync.aligned.m8n8.x4.shared.b16 {%0,%1,%2,%3}, [%4];" \
                 : "=r"(r0), "=r"(r1), "=r"(r2), "=r"(r3) : "r"(addr))

#define LDMX4T(r0, r1, r2, r3, addr) \
    asm volatile("ldmatrix.sync.aligned.m8n8.x4.trans.shared.b16 {%0,%1,%2,%3}, [%4];" \
                 : "=r"(r0), "=r"(r1), "=r"(r2), "=r"(r3) : "r"(addr))

#define MMA16816(C, A, b0, b1) \
    asm volatile("mma.sync.aligned.m16n8k16.row.col.f32.f16.f16.f32 " \
                 "{%0,%1,%2,%3}, {%4,%5,%6,%7}, {%8,%9}, {%0,%1,%2,%3};" \
                 : "+f"((C)[0]), "+f"((C)[1]), "+f"((C)[2]), "+f"((C)[3]) \
                 : "r"((A)[0]), "r"((A)[1]), "r"((A)[2]), "r"((A)[3]), \
                   "r"(b0), "r"(b1))

#define CP_ASYNC16(dst, src) \
    asm volatile("cp.async.cg.shared.global [%0], [%1], 16;" :: "r"(dst), "l"(src))
#define CP_COMMIT() asm volatile("cp.async.commit_group;")
#define CP_WAIT_ALL() asm volatile("cp.async.wait_group 0;")

__device__ __forceinline__ uint32_t pack_h2(float x, float y) {
    __half2 h = __floats2half2_rn(x, y);
    return *reinterpret_cast<uint32_t*>(&h);
}

// =============================================================
// fp32 -> fp16 convert, 4 elements/thread
// =============================================================
__global__ void __launch_bounds__(256) f2h_kernel(
    const float* __restrict__ src, __half* __restrict__ dst, int n4)
{
    int i = blockIdx.x * 256 + threadIdx.x;
    if (i < n4) {
        float4 v = ((const float4*)src)[i];
        ((half2*)dst)[2 * i]     = __floats2half2_rn(v.x, v.y);
        ((half2*)dst)[2 * i + 1] = __floats2half2_rn(v.z, v.w);
    }
}

// =============================================================
// Half GEMM: Y = A(fp16 MxK) @ W^T(fp16 NxK row-major) + bias
// Tile 128x128x64, 256 threads (8 warps: 4m x 2n), cp.async 2-stage.
// PROJ=1: write fp16 permuted per-head [b][h][s][dk]; PROJ=0: fp32 row-major.
// =============================================================
#define GBM 128
#define GBN 128
#define GBK 64
#define GPITCH 72
#define GSM_A 0
#define GSM_B (2 * GBM * GPITCH * 2)                 // 36864
#define GSM_TOTAL (GSM_B + 2 * GBN * GPITCH * 2)     // 73728

template <int PROJ>
__global__ void __launch_bounds__(256) hgemm_kernel(
    const __half* __restrict__ A, const __half* __restrict__ Bw,
    const float* __restrict__ bias, void* __restrict__ outp)
{
    extern __shared__ char gsm[];
    __half (*As)[GBM][GPITCH] = (__half(*)[GBM][GPITCH])(gsm + GSM_A);
    __half (*Bs)[GBN][GPITCH] = (__half(*)[GBN][GPITCH])(gsm + GSM_B);

    const int m0 = blockIdx.y * GBM;
    const int n0 = blockIdx.x * GBN;
    const int tid  = threadIdx.x;
    const int warp = tid >> 5;
    const int lane = tid & 31;
    const int wm = warp & 3, wn = warp >> 2;          // 4x2 warp grid
    const int g = lane >> 2, t = lane & 3;
    const int lrow = ((lane >> 3) & 1) * 8 + (lane & 7);
    const int lcol = (lane >> 4) * 8;

    float acc[2][8][4];
    #pragma unroll
    for (int i = 0; i < 2; i++)
        #pragma unroll
        for (int j = 0; j < 8; j++)
            #pragma unroll
            for (int e = 0; e < 4; e++) acc[i][j][e] = 0.0f;

    // prologue: stage 0
    {
        #pragma unroll
        for (int i = 0; i < 4; i++) {
            int idx = i * 256 + tid;                  // 0..1023
            int r = idx >> 3, c = (idx & 7) * 8;
            CP_ASYNC16(smem_u32(&As[0][r][c]), A  + (size_t)(m0 + r) * DMODEL + c);
            CP_ASYNC16(smem_u32(&Bs[0][r][c]), Bw + (size_t)(n0 + r) * DMODEL + c);
        }
        CP_COMMIT();
    }

    const int NKT = DMODEL / GBK;  // 16
    for (int kt = 0; kt < NKT; kt++) {
        const int st = kt & 1;
        CP_WAIT_ALL();
        __syncthreads();

        if (kt + 1 < NKT) {
            const int k1 = (kt + 1) * GBK;
            #pragma unroll
            for (int i = 0; i < 4; i++) {
                int idx = i * 256 + tid;
                int r = idx >> 3, c = (idx & 7) * 8;
                CP_ASYNC16(smem_u32(&As[st ^ 1][r][c]), A  + (size_t)(m0 + r) * DMODEL + k1 + c);
                CP_ASYNC16(smem_u32(&Bs[st ^ 1][r][c]), Bw + (size_t)(n0 + r) * DMODEL + k1 + c);
            }
            CP_COMMIT();
        }

        #pragma unroll
        for (int ks = 0; ks < 4; ks++) {
            uint32_t af[2][4];
            #pragma unroll
            for (int mf = 0; mf < 2; mf++) {
                uint32_t addr = smem_u32(&As[st][wm * 32 + mf * 16 + lrow][ks * 16 + lcol]);
                LDMX4(af[mf][0], af[mf][1], af[mf][2], af[mf][3], addr);
            }
            #pragma unroll
            for (int ng = 0; ng < 4; ng++) {
                uint32_t r0, r1, r2, r3;
                uint32_t addr = smem_u32(&Bs[st][wn * 64 + ng * 16 + lrow][ks * 16 + lcol]);
                LDMX4(r0, r1, r2, r3, addr);
                #pragma unroll
                for (int mf = 0; mf < 2; mf++) {
                    MMA16816(acc[mf][2 * ng],     af[mf], r0, r2);
                    MMA16816(acc[mf][2 * ng + 1], af[mf], r1, r3);
                }
            }
        }
        __syncthreads();
    }

    // epilogue: registers -> global, fused bias (+ permute for PROJ)
    #pragma unroll
    for (int mf = 0; mf < 2; mf++) {
        int row0 = m0 + wm * 32 + mf * 16 + g;
        int row1 = row0 + 8;
        #pragma unroll
        for (int nf = 0; nf < 8; nf++) {
            int col = n0 + wn * 64 + nf * 8 + 2 * t;
            float b0v = bias[col], b1v = bias[col + 1];
            float v00 = acc[mf][nf][0] + b0v, v01 = acc[mf][nf][1] + b1v;
            float v10 = acc[mf][nf][2] + b0v, v11 = acc[mf][nf][3] + b1v;
            if (PROJ) {
                __half* out = (__half*)outp;
                int h = col >> 6, dk = col & 63;
                int s0 = row0 >> 1, bb0 = row0 & 1;
                int s1 = row1 >> 1, bb1 = row1 & 1;
                *(__half2*)(out + ((((size_t)bb0 * NHEAD + h) * S_LEN + s0) << 6) + dk) =
                    __floats2half2_rn(v00, v01);
                *(__half2*)(out + ((((size_t)bb1 * NHEAD + h) * S_LEN + s1) << 6) + dk) =
                    __floats2half2_rn(v10, v11);
            } else {
                float* out = (float*)outp;
                *(float2*)(out + (size_t)row0 * DMODEL + col) = make_float2(v00, v01);
                *(float2*)(out + (size_t)row1 * DMODEL + col) = make_float2(v10, v11);
            }
        }
    }
}

// =============================================================
// Register-resident flash attention (unchanged from R1).
// Block: 256 threads (8 warps), Q tile 128 rows, KV tile 64.
// =============================================================
#define BQ 128
#define BK 64
#define APITCH 72

#define SM_Q  0
#define SM_K  (BQ * APITCH * 2)                    // 18432
#define SM_V  (SM_K + 2 * BK * APITCH * 2)
#define SM_ATTN_TOTAL (SM_V + 2 * BK * APITCH * 2) // 55296

__global__ void __launch_bounds__(256) attn_kernel(
    const __half* __restrict__ Qg_, const __half* __restrict__ Kg_,
    const __half* __restrict__ Vg_, __half* __restrict__ ctx)
{
    extern __shared__ char smb[];
    __half (*Qs)[APITCH] = (__half(*)[APITCH])(smb + SM_Q);
    __half (*Ks)[BK][APITCH] = (__half(*)[BK][APITCH])(smb + SM_K);
    __half (*Vs)[BK][APITCH] = (__half(*)[BK][APITCH])(smb + SM_V);

    const int q0 = blockIdx.x * BQ;
    const int h  = blockIdx.y;
    const int b  = blockIdx.z;
    const size_t head_off = ((size_t)b * NHEAD + h) * S_LEN * DKH;
    const __half* Qg = Qg_ + head_off;
    const __half* Kg = Kg_ + head_off;
    const __half* Vg = Vg_ + head_off;

    const int tid  = threadIdx.x;
    const int warp = tid >> 5;
    const int lane = tid & 31;
    const int g = lane >> 2;
    const int t = lane & 3;

    #pragma unroll
    for (int i = 0; i < 4; i++) {
        int idx = i * 256 + tid;
        int r = idx >> 3, c8 = (idx & 7) * 8;
        *(uint4*)&Qs[r][c8] = *(const uint4*)(Qg + (size_t)(q0 + r) * DKH + c8);
    }

    {
        #pragma unroll
        for (int i = 0; i < 2; i++) {
            int idx = i * 256 + tid;
            int r = idx >> 3, c = (idx & 7) * 8;
            CP_ASYNC16(smem_u32(&Ks[0][r][c]), Kg + (size_t)r * DKH + c);
            CP_ASYNC16(smem_u32(&Vs[0][r][c]), Vg + (size_t)r * DKH + c);
        }
        CP_COMMIT();
    }
    __syncthreads();

    uint32_t qf[4][4];
    {
        int lr = warp * 16 + ((lane >> 3) & 1) * 8 + (lane & 7);
        int lc = (lane >> 4) * 8;
        #pragma unroll
        for (int u = 0; u < 4; u++) {
            uint32_t addr = smem_u32(&Qs[lr][16 * u + lc]);
            LDMX4(qf[u][0], qf[u][1], qf[u][2], qf[u][3], addr);
        }
    }

    float m0 = -1e30f, m1 = -1e30f, l0 = 0.0f, l1 = 0.0f;
    float o[8][4];
    #pragma unroll
    for (int j = 0; j < 8; j++)
        #pragma unroll
        for (int e = 0; e < 4; e++) o[j][e] = 0.0f;

    const int lrow = ((lane >> 3) & 1) * 8 + (lane & 7);
    const int lcol = (lane >> 4) * 8;

    const int NT = S_LEN / BK;
    for (int it = 0; it < NT; ++it) {
        const int st = it & 1;
        CP_WAIT_ALL();
        __syncthreads();

        if (it + 1 < NT) {
            const int j1 = (it + 1) * BK;
            #pragma unroll
            for (int i = 0; i < 2; i++) {
                int idx = i * 256 + tid;
                int r = idx >> 3, c = (idx & 7) * 8;
                CP_ASYNC16(smem_u32(&Ks[st ^ 1][r][c]), Kg + (size_t)(j1 + r) * DKH + c);
                CP_ASYNC16(smem_u32(&Vs[st ^ 1][r][c]), Vg + (size_t)(j1 + r) * DKH + c);
            }
            CP_COMMIT();
        }

        float sc[8][4];
        #pragma unroll
        for (int j = 0; j < 8; j++)
            #pragma unroll
            for (int e = 0; e < 4; e++) sc[j][e] = 0.0f;

        #pragma unroll
        for (int kg = 0; kg < 4; kg++) {
            #pragma unroll
            for (int u = 0; u < 4; u++) {
                uint32_t r0, r1, r2, r3;
                uint32_t addr = smem_u32(&Ks[st][16 * kg + lrow][16 * u + lcol]);
                LDMX4(r0, r1, r2, r3, addr);
                MMA16816(sc[2 * kg],     qf[u], r0, r2);
                MMA16816(sc[2 * kg + 1], qf[u], r1, r3);
            }
        }

        #pragma unroll
        for (int j = 0; j < 8; j++)
            #pragma unroll
            for (int e = 0; e < 4; e++) sc[j][e] *= SCALE;

        float mt0 = -1e30f, mt1 = -1e30f;
        #pragma unroll
        for (int j = 0; j < 8; j++) {
            mt0 = fmaxf(mt0, fmaxf(sc[j][0], sc[j][1]));
            mt1 = fmaxf(mt1, fmaxf(sc[j][2], sc[j][3]));
        }
        mt0 = fmaxf(mt0, __shfl_xor_sync(0xffffffffu, mt0, 1));
        mt0 = fmaxf(mt0, __shfl_xor_sync(0xffffffffu, mt0, 2));
        mt1 = fmaxf(mt1, __shfl_xor_sync(0xffffffffu, mt1, 1));
        mt1 = fmaxf(mt1, __shfl_xor_sync(0xffffffffu, mt1, 2));

        float mn0 = fmaxf(m0, mt0), mn1 = fmaxf(m1, mt1);
        float a0 = __expf(m0 - mn0), a1 = __expf(m1 - mn1);
        m0 = mn0; m1 = mn1;

        float s0 = 0.0f, s1 = 0.0f;
        uint32_t pf[4][4];
        #pragma unroll
        for (int j = 0; j < 8; j++) {
            float p0 = __expf(sc[j][0] - m0);
            float p1 = __expf(sc[j][1] - m0);
            float p2 = __expf(sc[j][2] - m1);
            float p3 = __expf(sc[j][3] - m1);
            s0 += p0 + p1;
            s1 += p2 + p3;
            int u = j >> 1, hi = j & 1;
            pf[u][2 * hi]     = pack_h2(p0, p1);
            pf[u][2 * hi + 1] = pack_h2(p2, p3);
        }
        s0 += __shfl_xor_sync(0xffffffffu, s0, 1);
        s0 += __shfl_xor_sync(0xffffffffu, s0, 2);
        s1 += __shfl_xor_sync(0xffffffffu, s1, 1);
        s1 += __shfl_xor_sync(0xffffffffu, s1, 2);
        l0 = l0 * a0 + s0;
        l1 = l1 * a1 + s1;

        #pragma unroll
        for (int j = 0; j < 8; j++) {
            o[j][0] *= a0; o[j][1] *= a0;
            o[j][2] *= a1; o[j][3] *= a1;
        }

        #pragma unroll
        for (int u = 0; u < 4; u++) {
            #pragma unroll
            for (int jp = 0; jp < 4; jp++) {
                uint32_t r0, r1, r2, r3;
                uint32_t addr = smem_u32(&Vs[st][16 * u + lrow][16 * jp + lcol]);
                LDMX4T(r0, r1, r2, r3, addr);
                MMA16816(o[2 * jp],     pf[u], r0, r1);
                MMA16816(o[2 * jp + 1], pf[u], r2, r3);
            }
        }
    }

    float inv0 = 1.0f / l0, inv1 = 1.0f / l1;
    int s_row0 = q0 + warp * 16 + g;
    int s_row1 = s_row0 + 8;
    __half* base0 = ctx + ((size_t)s_row0 * BATCH + b) * DMODEL + h * DKH;
    __half* base1 = ctx + ((size_t)s_row1 * BATCH + b) * DMODEL + h * DKH;
    #pragma unroll
    for (int j = 0; j < 8; j++) {
        int c = 8 * j + 2 * t;
        *(__half2*)(base0 + c) = __floats2half2_rn(o[j][0] * inv0, o[j][1] * inv0);
        *(__half2*)(base1 + c) = __floats2half2_rn(o[j][2] * inv1, o[j][3] * inv1);
    }
}

// =============================================================
extern "C" void kernel_launch(void* const* d_in, const int* in_sizes, int n_in,
                              void* d_out, int out_size)
{
    const float* q  = (const float*)d_in[0];
    const float* k  = (const float*)d_in[1];
    const float* v  = (const float*)d_in[2];
    const float* wq = (const float*)d_in[3];
    const float* bq = (const float*)d_in[4];
    const float* wk = (const float*)d_in[5];
    const float* bk = (const float*)d_in[6];
    const float* wv = (const float*)d_in[7];
    const float* bv = (const float*)d_in[8];
    const float* wo = (const float*)d_in[9];
    const float* bo = (const float*)d_in[10];
    float* out = (float*)d_out;

    void *pQ, *pK, *pV, *pC, *pXq, *pXk, *pXv, *pWq, *pWk, *pWv, *pWo;
    cudaGetSymbolAddress(&pQ, g_Q);
    cudaGetSymbolAddress(&pK, g_K);
    cudaGetSymbolAddress(&pV, g_V);
    cudaGetSymbolAddress(&pC, g_ctx);
    cudaGetSymbolAddress(&pXq, g_Xq);
    cudaGetSymbolAddress(&pXk, g_Xk);
    cudaGetSymbolAddress(&pXv, g_Xv);
    cudaGetSymbolAddress(&pWq, g_Wq);
    cudaGetSymbolAddress(&pWk, g_Wk);
    cudaGetSymbolAddress(&pWv, g_Wv);
    cudaGetSymbolAddress(&pWo, g_Wo);

    cudaFuncSetAttribute(attn_kernel, cudaFuncAttributeMaxDynamicSharedMemorySize,
                         SM_ATTN_TOTAL);
    cudaFuncSetAttribute(hgemm_kernel<1>, cudaFuncAttributeMaxDynamicSharedMemorySize,
                         GSM_TOTAL);
    cudaFuncSetAttribute(hgemm_kernel<0>, cudaFuncAttributeMaxDynamicSharedMemorySize,
                         GSM_TOTAL);

    // fp32 -> fp16 conversions
    const int nx4 = MROWS * DMODEL / 4;     // 1M
    const int nw4 = DMODEL * DMODEL / 4;    // 256K
    f2h_kernel<<<nx4 / 256, 256>>>(q,  (__half*)pXq, nx4);
    f2h_kernel<<<nx4 / 256, 256>>>(k,  (__half*)pXk, nx4);
    f2h_kernel<<<nx4 / 256, 256>>>(v,  (__half*)pXv, nx4);
    f2h_kernel<<<nw4 / 256, 256>>>(wq, (__half*)pWq, nw4);
    f2h_kernel<<<nw4 / 256, 256>>>(wk, (__half*)pWk, nw4);
    f2h_kernel<<<nw4 / 256, 256>>>(wv, (__half*)pWv, nw4);
    f2h_kernel<<<nw4 / 256, 256>>>(wo, (__half*)pWo, nw4);

    // QKV projections
    dim3 gg(DMODEL / GBN, MROWS / GBM);     // (8, 32)
    hgemm_kernel<1><<<gg, 256, GSM_TOTAL>>>((const __half*)pXq, (const __half*)pWq, bq, pQ);
    hgemm_kernel<1><<<gg, 256, GSM_TOTAL>>>((const __half*)pXk, (const __half*)pWk, bk, pK);
    hgemm_kernel<1><<<gg, 256, GSM_TOTAL>>>((const __half*)pXv, (const __half*)pWv, bv, pV);

    // attention
    dim3 ga(S_LEN / BQ, NHEAD, BATCH);      // (16, 16, 2)
    attn_kernel<<<ga, 256, SM_ATTN_TOTAL>>>((const __half*)pQ, (const __half*)pK,
                                            (const __half*)pV, (__half*)pC);

    // output projection
    hgemm_kernel<0><<<gg, 256, GSM_TOTAL>>>((const __half*)pC, (const __half*)pWo, bo, out);
}